// round 12
// baseline (speedup 1.0000x reference)
#include <cuda_runtime.h>
#include <math.h>

#define BB 2
#define LL 4096
#define DM 64
#define DI 128
#define NN 16
#define RR 4
#define K4 4
#define NC 128  // number of chunks
#define CH 32   // chunk length (NC*CH == LL)
#define CPL (NC/32)  // chunks per lane in k_comb

typedef unsigned long long u64;

__device__ __forceinline__ u64 pk2(float lo, float hi) {
    u64 r; asm("mov.b64 %0,{%1,%2};" : "=l"(r) : "f"(lo), "f"(hi)); return r;
}
__device__ __forceinline__ void upk2(float& lo, float& hi, u64 v) {
    asm("mov.b64 {%0,%1},%2;" : "=f"(lo), "=f"(hi) : "l"(v));
}
__device__ __forceinline__ u64 fma2(u64 a, u64 b, u64 c) {
    u64 d; asm("fma.rn.f32x2 %0,%1,%2,%3;" : "=l"(d) : "l"(a), "l"(b), "l"(c)); return d;
}
__device__ __forceinline__ u64 mul2(u64 a, u64 b) {
    u64 d; asm("mul.rn.f32x2 %0,%1,%2;" : "=l"(d) : "l"(a), "l"(b)); return d;
}

// softplus + exp(-softplus) via sigmoid identity:
// p = exp(-softplus(u)) = 1/(1+e^u), delta = -log(p)
__device__ __forceinline__ void softplus_pair(float u, float& delta, float& p) {
    float t = __expf(fminf(u, 20.f));
    p = __fdividef(1.f, 1.f + t);
    delta = (u > 20.f) ? u : -__logf(p);
}

// ---------------- scratch ----------------
__device__ float g_z  [BB*LL*DI];
__device__ float g_xc [BB*LL*DI];
__device__ float g_xs [BB*K4*LL*DI];
__device__ float g_u  [BB*K4*LL*DI];
__device__ float g_Bv [BB*K4*LL*NN];
__device__ float g_Cv [BB*K4*LL*NN];
__device__ float g_y  [BB*K4*LL*DI];
__device__ float g_cumP[BB*K4*LL*DI];
__device__ float g_hend[BB*K4*NC*DI*NN];
__device__ float g_Ptot[BB*K4*NC*DI];
__device__ float g_h0  [BB*K4*NC*DI*NN];
__device__ float g_yln [BB*LL*DI];

// ---------------- K1: reverse3d + in_proj GEMM + depthwise conv + SiLU (fused) ----------------
__global__ void k_inproj(const float* __restrict__ x, const float* __restrict__ W,
                         const float* __restrict__ cw, const float* __restrict__ cb) {
    __shared__ float xr[34*64];   // rows row0-1 .. row0+32
    int co = threadIdx.x;
    float4 w[16];
    #pragma unroll
    for (int j = 0; j < 16; j++) w[j] = reinterpret_cast<const float4*>(W)[co*16 + j];
    int row0 = blockIdx.x * 32;
    for (int i = threadIdx.x; i < 34*64; i += 256) {
        int r = i >> 6, c = i & 63;
        int bl = row0 + r - 1;
        float v = 0.f;
        bool valid = true;
        if (r == 0  && (row0 & (LL-1)) == 0)        valid = false;  // l = -1
        if (r == 33 && ((row0 + 32) & (LL-1)) == 0) valid = false;  // l = LL
        if (valid) {
            int b = bl >> 12, l = bl & (LL-1);
            int cs = ((l + b) & 1) ? (63 - c) : c;
            v = x[bl*64 + cs];
        }
        xr[r*64 + c] = v;
    }
    __syncthreads();
    float w0 = 0.f, w1 = 0.f, w2 = 0.f, bias = 0.f;
    if (co < DI) { w0 = cw[co*3]; w1 = cw[co*3+1]; w2 = cw[co*3+2]; bias = cb[co]; }
    float a0 = 0.f, a1 = 0.f;
    for (int j = 0; j < 34; j++) {
        const float4* xv = reinterpret_cast<const float4*>(xr + j*64);
        float acc = 0.f;
        #pragma unroll
        for (int t = 0; t < 16; t++) {
            float4 a = w[t], q = xv[t];
            acc = fmaf(a.x,q.x,acc); acc = fmaf(a.y,q.y,acc);
            acc = fmaf(a.z,q.z,acc); acc = fmaf(a.w,q.w,acc);
        }
        if (co < DI) {
            if (j >= 2) {
                float v = bias;
                v = fmaf(w0, a0, v); v = fmaf(w1, a1, v); v = fmaf(w2, acc, v);
                float sg = __fdividef(1.f, 1.f + __expf(-v));
                g_xc[(row0 + j - 2)*DI + co] = v * sg;
            }
            a0 = a1; a1 = acc;
        } else {
            if (j >= 1 && j <= 32) g_z[(row0 + j - 1)*DI + (co - DI)] = acc;
        }
    }
}

// ---------------- K3: zigzag gather + x_proj + dt_proj ----------------
__global__ void k_proj(const int* __restrict__ zig, const float* __restrict__ xpw,
                       const float* __restrict__ dtw, const float* __restrict__ dtb) {
    __shared__ float s_xpw[36*DI];
    __shared__ float s_dtw[DI*RR];
    __shared__ float s_db[DI];
    int bk = blockIdx.y; int b = bk >> 2; int k = bk & 3;
    for (int i = threadIdx.x; i < 36*DI; i += 256) s_xpw[i] = xpw[k*36*DI + i];
    for (int i = threadIdx.x; i < DI*RR; i += 256) s_dtw[i] = dtw[k*DI*RR + i];
    for (int i = threadIdx.x; i < DI;    i += 256) s_db[i]  = dtb[k*DI + i];
    __syncthreads();
    int warp = threadIdx.x >> 5, lane = threadIdx.x & 31;
    int l = blockIdx.x * 8 + warp;
    int src = zig[k*LL + l];
    const float* xrow = g_xc + (b*LL + src)*DI;
    float x0 = xrow[lane], x1 = xrow[lane+32], x2 = xrow[lane+64], x3 = xrow[lane+96];
    int obase = (bk*LL + l)*DI;
    g_xs[obase+lane] = x0; g_xs[obase+lane+32] = x1;
    g_xs[obase+lane+64] = x2; g_xs[obase+lane+96] = x3;
    float dtr0=0.f, dtr1=0.f, dtr2=0.f, dtr3=0.f, Bval=0.f, Cval=0.f;
    #pragma unroll
    for (int c = 0; c < 36; c++) {
        const float* wp = s_xpw + c*DI + lane;
        float part = wp[0]*x0 + wp[32]*x1 + wp[64]*x2 + wp[96]*x3;
        part += __shfl_xor_sync(0xffffffffu, part, 16);
        part += __shfl_xor_sync(0xffffffffu, part, 8);
        part += __shfl_xor_sync(0xffffffffu, part, 4);
        part += __shfl_xor_sync(0xffffffffu, part, 2);
        part += __shfl_xor_sync(0xffffffffu, part, 1);
        if      (c == 0) dtr0 = part;
        else if (c == 1) dtr1 = part;
        else if (c == 2) dtr2 = part;
        else if (c == 3) dtr3 = part;
        else if (c < 20) { if (lane == c-4)  Bval = part; }
        else             { if (lane == c-20) Cval = part; }
    }
    if (lane < NN) {
        g_Bv[(bk*LL + l)*NN + lane] = Bval;
        g_Cv[(bk*LL + l)*NN + lane] = Cval;
    }
    #pragma unroll
    for (int j = 0; j < 4; j++) {
        int d = lane + 32*j;
        float u = s_db[d];
        u = fmaf(dtr0, s_dtw[d*RR+0], u);
        u = fmaf(dtr1, s_dtw[d*RR+1], u);
        u = fmaf(dtr2, s_dtw[d*RR+2], u);
        u = fmaf(dtr3, s_dtw[d*RR+3], u);
        g_u[obase + d] = u;
    }
}

// ---------------- K4: scan phase 1 (chunk-local), f32x2 fast path ----------------
__global__ void __launch_bounds__(DI) k_scan1(const float* __restrict__ A_logs,
                                              const float* __restrict__ Ds) {
    __shared__ __align__(16) float sB[CH*NN];
    __shared__ __align__(16) float sC[CH*NN];
    int c = blockIdx.x, bk = blockIdx.y;
    int k = bk & 3, d = threadIdx.x;
    int l0 = c*CH;
    for (int i = d; i < CH*NN; i += DI) {
        sB[i] = g_Bv[(bk*LL + l0)*NN + i];
        sC[i] = g_Cv[(bk*LL + l0)*NN + i];
    }
    float An[NN]; bool fast = true;
    #pragma unroll
    for (int n = 0; n < NN; n++) {
        An[n] = -__expf(A_logs[(k*DI + d)*NN + n]);
        if (fabsf(An[n] + (float)(n+1)) > 1e-3f) fast = false;
    }
    float Dval = Ds[k*DI + d];
    __syncthreads();
    float cum = 1.f;
    int base = (bk*LL + l0)*DI + d;
    int cidx = (bk*NC + c)*DI + d;
    if (fast) {
        u64 h2[NN/2];
        #pragma unroll
        for (int j = 0; j < NN/2; j++) h2[j] = 0ull;
        #pragma unroll 4
        for (int s = 0; s < CH; s++) {
            int idx = base + s*DI;
            float u = g_u[idx], xv = g_xs[idx];
            float delta, p;
            softplus_pair(u, delta, p);
            float du = delta * xv;
            cum *= p;
            g_cumP[idx] = cum;
            float psq = p*p;
            u64 p2d = pk2(psq, psq);
            u64 pn  = pk2(p, psq);
            u64 du2 = pk2(du, du);
            u64 y2  = 0ull;
            const u64* B2 = reinterpret_cast<const u64*>(sB + s*NN);
            const u64* C2 = reinterpret_cast<const u64*>(sC + s*NN);
            #pragma unroll
            for (int j = 0; j < NN/2; j++) {
                if (j) pn = mul2(pn, p2d);
                h2[j] = fma2(h2[j], pn, mul2(du2, B2[j]));
                y2 = fma2(h2[j], C2[j], y2);
            }
            float ylo, yhi; upk2(ylo, yhi, y2);
            g_y[idx] = fmaf(Dval, xv, ylo + yhi);
        }
        u64* hd = reinterpret_cast<u64*>(g_hend + cidx*NN);
        #pragma unroll
        for (int j = 0; j < NN/2; j++) hd[j] = h2[j];
    } else {
        float h[NN];
        #pragma unroll
        for (int n = 0; n < NN; n++) h[n] = 0.f;
        for (int s = 0; s < CH; s++) {
            int idx = base + s*DI;
            float u = g_u[idx], xv = g_xs[idx];
            float delta, p;
            softplus_pair(u, delta, p);
            float du = delta * xv;
            cum *= p;
            g_cumP[idx] = cum;
            float y = 0.f;
            #pragma unroll
            for (int n = 0; n < NN; n++) {
                float dA = __expf(delta * An[n]);
                h[n] = fmaf(h[n], dA, du * sB[s*NN + n]);
                y = fmaf(h[n], sC[s*NN + n], y);
            }
            g_y[idx] = fmaf(Dval, xv, y);
        }
        #pragma unroll
        for (int n = 0; n < NN; n++) g_hend[cidx*NN + n] = h[n];
    }
    g_Ptot[cidx] = cum;
}

// ---------------- K5: chunk combine — warp-shuffle two-level scan ----------------
// one warp per (bk,d) lane; 4 chunks per thread; block 256 = 8 warps
__global__ void __launch_bounds__(256) k_comb(const float* __restrict__ A_logs) {
    int gw = (blockIdx.x * 256 + threadIdx.x) >> 5;  // 0 .. BB*K4*DI-1
    int lane = threadIdx.x & 31;
    int bk = gw >> 7;
    int d  = gw & (DI-1);
    int k  = bk & 3;

    float An[NN]; bool fast = true;
    #pragma unroll
    for (int n = 0; n < NN; n++) {
        An[n] = -__expf(__ldg(&A_logs[(k*DI + d)*NN + n]));
        if (fabsf(An[n] + (float)(n+1)) > 1e-3f) fast = false;
    }
    int base = bk*NC*DI + d;
    int c0 = lane * CPL;

    // Phase A: serial segment aggregate over this lane's CPL chunks
    float F[NN], H[NN];
    #pragma unroll
    for (int n = 0; n < NN; n++) { F[n] = 1.f; H[n] = 0.f; }
    #pragma unroll
    for (int j = 0; j < CPL; j++) {
        int cidx = base + (c0 + j)*DI;
        float P = __ldg(&g_Ptot[cidx]);
        const float4* he4 = reinterpret_cast<const float4*>(g_hend + (size_t)cidx*NN);
        float4 e0 = __ldg(he4+0), e1 = __ldg(he4+1), e2 = __ldg(he4+2), e3 = __ldg(he4+3);
        float he[NN] = {e0.x,e0.y,e0.z,e0.w, e1.x,e1.y,e1.z,e1.w,
                        e2.x,e2.y,e2.z,e2.w, e3.x,e3.y,e3.z,e3.w};
        float f[NN];
        if (fast) {
            float pw = P; f[0] = P;
            #pragma unroll
            for (int n = 1; n < NN; n++) { pw *= P; f[n] = pw; }
        } else {
            #pragma unroll
            for (int n = 0; n < NN; n++)
                f[n] = (P > 0.f) ? __powf(P, -An[n]) : 0.f;
        }
        #pragma unroll
        for (int n = 0; n < NN; n++) {
            H[n] = fmaf(f[n], H[n], he[n]);
            F[n] *= f[n];
        }
    }

    // Phase B: warp-level inclusive scan of (F,H)
    #pragma unroll
    for (int st = 1; st < 32; st <<= 1) {
        float flo[NN], hlo[NN];
        #pragma unroll
        for (int n = 0; n < NN; n++) {
            flo[n] = __shfl_up_sync(0xffffffffu, F[n], st);
            hlo[n] = __shfl_up_sync(0xffffffffu, H[n], st);
        }
        if (lane >= st) {
            #pragma unroll
            for (int n = 0; n < NN; n++) {
                H[n] = fmaf(F[n], hlo[n], H[n]);
                F[n] *= flo[n];
            }
        }
    }

    // Phase C: exclusive prefix at segment start, then replay chunks
    float pre[NN];
    #pragma unroll
    for (int n = 0; n < NN; n++) {
        float v = __shfl_up_sync(0xffffffffu, H[n], 1);
        pre[n] = lane ? v : 0.f;
    }
    #pragma unroll
    for (int j = 0; j < CPL; j++) {
        int cidx = base + (c0 + j)*DI;
        float4* h04 = reinterpret_cast<float4*>(g_h0 + (size_t)cidx*NN);
        h04[0] = make_float4(pre[0],  pre[1],  pre[2],  pre[3]);
        h04[1] = make_float4(pre[4],  pre[5],  pre[6],  pre[7]);
        h04[2] = make_float4(pre[8],  pre[9],  pre[10], pre[11]);
        h04[3] = make_float4(pre[12], pre[13], pre[14], pre[15]);
        if (j < CPL-1) {
            float P = __ldg(&g_Ptot[cidx]);
            const float4* he4 = reinterpret_cast<const float4*>(g_hend + (size_t)cidx*NN);
            float4 e0 = __ldg(he4+0), e1 = __ldg(he4+1), e2 = __ldg(he4+2), e3 = __ldg(he4+3);
            float he[NN] = {e0.x,e0.y,e0.z,e0.w, e1.x,e1.y,e1.z,e1.w,
                            e2.x,e2.y,e2.z,e2.w, e3.x,e3.y,e3.z,e3.w};
            float f[NN];
            if (fast) {
                float pw = P; f[0] = P;
                #pragma unroll
                for (int n = 1; n < NN; n++) { pw *= P; f[n] = pw; }
            } else {
                #pragma unroll
                for (int n = 0; n < NN; n++)
                    f[n] = (P > 0.f) ? __powf(P, -An[n]) : 0.f;
            }
            #pragma unroll
            for (int n = 0; n < NN; n++)
                pre[n] = fmaf(f[n], pre[n], he[n]);
        }
    }
}

// ---------------- K6: correction, f32x2 fast path ----------------
__global__ void __launch_bounds__(DI) k_corr(const float* __restrict__ A_logs) {
    __shared__ __align__(16) float sC[CH*NN];
    int c = blockIdx.x + 1, bk = blockIdx.y;
    int k = bk & 3, d = threadIdx.x;
    int l0 = c*CH;
    for (int i = d; i < CH*NN; i += DI) sC[i] = g_Cv[(bk*LL + l0)*NN + i];
    float An[NN]; bool fast = true;
    #pragma unroll
    for (int n = 0; n < NN; n++) {
        An[n] = -__expf(A_logs[(k*DI + d)*NN + n]);
        if (fabsf(An[n] + (float)(n+1)) > 1e-3f) fast = false;
    }
    int cidx = (bk*NC + c)*DI + d;
    float h0[NN];
    #pragma unroll
    for (int n = 0; n < NN; n++) h0[n] = g_h0[cidx*NN + n];
    __syncthreads();
    int base = (bk*LL + l0)*DI + d;
    if (fast) {
        u64 h02[NN/2];
        #pragma unroll
        for (int j = 0; j < NN/2; j++) h02[j] = pk2(h0[2*j], h0[2*j+1]);
        #pragma unroll 4
        for (int s = 0; s < CH; s++) {
            int idx = base + s*DI;
            float cp = g_cumP[idx];
            float cpsq = cp*cp;
            u64 sq2 = pk2(cpsq, cpsq);
            u64 pn  = pk2(cp, cpsq);
            u64 acc2 = 0ull;
            const u64* C2 = reinterpret_cast<const u64*>(sC + s*NN);
            #pragma unroll
            for (int j = 0; j < NN/2; j++) {
                if (j) pn = mul2(pn, sq2);
                acc2 = fma2(pn, mul2(h02[j], C2[j]), acc2);
            }
            float lo, hi; upk2(lo, hi, acc2);
            g_y[idx] += lo + hi;
        }
    } else {
        for (int s = 0; s < CH; s++) {
            int idx = base + s*DI;
            float cp = g_cumP[idx];
            float acc = 0.f;
            if (cp > 0.f) {
                #pragma unroll
                for (int n = 0; n < NN; n++)
                    acc = fmaf(__powf(cp, -An[n]), h0[n]*sC[s*NN+n], acc);
            }
            g_y[idx] += acc;
        }
    }
}

// ---------------- K7: inverse zigzag sum + LayerNorm + silu(z) gate ----------------
__global__ void k_gln(const int* __restrict__ zb, const float* __restrict__ lnw,
                      const float* __restrict__ lnb) {
    int bl = blockIdx.x;
    int b = bl >> 12, l = bl & (LL-1);
    int d = threadIdx.x;
    float acc = 0.f;
    #pragma unroll
    for (int i = 0; i < 8; i++) {
        int kk = i & 3;
        int src = zb[i*LL + l];
        acc += g_y[((b*K4 + kk)*LL + src)*DI + d];
    }
    float s1 = acc, s2 = acc*acc;
    #pragma unroll
    for (int o = 16; o > 0; o >>= 1) {
        s1 += __shfl_xor_sync(0xffffffffu, s1, o);
        s2 += __shfl_xor_sync(0xffffffffu, s2, o);
    }
    __shared__ float r1[4], r2[4];
    int warp = d >> 5, lane = d & 31;
    if (lane == 0) { r1[warp] = s1; r2[warp] = s2; }
    __syncthreads();
    float S1 = r1[0]+r1[1]+r1[2]+r1[3];
    float S2 = r2[0]+r2[1]+r2[2]+r2[3];
    float mu = S1 * (1.f/DI);
    float var = S2 * (1.f/DI) - mu*mu;
    float yn = (acc - mu) * rsqrtf(var + 1e-5f) * lnw[d] + lnb[d];
    float zv = g_z[bl*DI + d];
    float sg = __fdividef(1.f, 1.f + __expf(-zv));
    g_yln[bl*DI + d] = yn * (zv * sg);
}

// ---------------- K8: out_proj GEMM + reverse3d, 32-row amortized ----------------
__global__ void k_out(const float* __restrict__ Wout, float* __restrict__ out) {
    __shared__ float s_y[32*DI];
    __shared__ float s_part[32*DI];
    int t = threadIdx.x;                 // 128
    int bl0 = blockIdx.x * 32;
    const float4* src = reinterpret_cast<const float4*>(g_yln + bl0*DI);
    float4* dst = reinterpret_cast<float4*>(s_y);
    #pragma unroll
    for (int i = 0; i < 8; i++) dst[t + 128*i] = src[t + 128*i];
    int co = t & 63, half = t >> 6;
    float4 w[16];
    const float4* wp = reinterpret_cast<const float4*>(Wout + co*DI + half*64);
    #pragma unroll
    for (int j = 0; j < 16; j++) w[j] = wp[j];
    __syncthreads();
    for (int r = 0; r < 32; r++) {
        const float4* yv = reinterpret_cast<const float4*>(s_y + r*DI + half*64);
        float acc = 0.f;
        #pragma unroll
        for (int j = 0; j < 16; j++) {
            float4 a = w[j], q = yv[j];
            acc = fmaf(a.x,q.x,acc); acc = fmaf(a.y,q.y,acc);
            acc = fmaf(a.z,q.z,acc); acc = fmaf(a.w,q.w,acc);
        }
        s_part[r*DI + t] = acc;
    }
    __syncthreads();
    for (int i = t; i < 32*64; i += 128) {
        int r = i >> 6, c = i & 63;
        float v = s_part[r*DI + c] + s_part[r*DI + 64 + c];
        int bl = bl0 + r;
        int b = bl >> 12, l = bl & (LL-1);
        int cdst = ((l + b) & 1) ? (63 - c) : c;
        out[bl*DM + cdst] = v;
    }
}

// ---------------- launch ----------------
extern "C" void kernel_launch(void* const* d_in, const int* in_sizes, int n_in,
                              void* d_out, int out_size) {
    const float* x        = (const float*)d_in[0];
    const int*   zig_path = (const int*)  d_in[1];
    const int*   zig_back = (const int*)  d_in[2];
    const float* in_proj  = (const float*)d_in[3];
    const float* conv_w   = (const float*)d_in[4];
    const float* conv_b   = (const float*)d_in[5];
    const float* xpw      = (const float*)d_in[6];
    const float* dtw      = (const float*)d_in[7];
    const float* dtb      = (const float*)d_in[8];
    const float* A_logs   = (const float*)d_in[9];
    const float* Ds       = (const float*)d_in[10];
    const float* lnw      = (const float*)d_in[11];
    const float* lnb      = (const float*)d_in[12];
    const float* outw     = (const float*)d_in[13];
    float* out = (float*)d_out;

    k_inproj<<<(BB*LL)/32, 256>>>(x, in_proj, conv_w, conv_b);
    k_proj  <<<dim3(LL/8, BB*K4), 256>>>(zig_path, xpw, dtw, dtb);
    k_scan1 <<<dim3(NC, BB*K4), DI>>>(A_logs, Ds);
    k_comb  <<<(BB*K4*DI*32)/256, 256>>>(A_logs);
    k_corr  <<<dim3(NC-1, BB*K4), DI>>>(A_logs);
    k_gln   <<<BB*LL, DI>>>(zig_back, lnw, lnb);
    k_out   <<<(BB*LL)/32, 128>>>(outw, out);
}

// round 13
// speedup vs baseline: 1.0014x; 1.0014x over previous
#include <cuda_runtime.h>
#include <math.h>

#define BB 2
#define LL 4096
#define DM 64
#define DI 128
#define NN 16
#define RR 4
#define K4 4
#define NC 128  // number of chunks
#define CH 32   // chunk length (NC*CH == LL)
#define CPL (NC/32)  // chunks per lane in k_comb

typedef unsigned long long u64;

__device__ __forceinline__ u64 pk2(float lo, float hi) {
    u64 r; asm("mov.b64 %0,{%1,%2};" : "=l"(r) : "f"(lo), "f"(hi)); return r;
}
__device__ __forceinline__ void upk2(float& lo, float& hi, u64 v) {
    asm("mov.b64 {%0,%1},%2;" : "=f"(lo), "=f"(hi) : "l"(v));
}
__device__ __forceinline__ u64 fma2(u64 a, u64 b, u64 c) {
    u64 d; asm("fma.rn.f32x2 %0,%1,%2,%3;" : "=l"(d) : "l"(a), "l"(b), "l"(c)); return d;
}
__device__ __forceinline__ u64 mul2(u64 a, u64 b) {
    u64 d; asm("mul.rn.f32x2 %0,%1,%2;" : "=l"(d) : "l"(a), "l"(b)); return d;
}

// softplus + exp(-softplus) via sigmoid identity:
// p = exp(-softplus(u)) = 1/(1+e^u), delta = -log(p)
__device__ __forceinline__ void softplus_pair(float u, float& delta, float& p) {
    float t = __expf(fminf(u, 20.f));
    p = __fdividef(1.f, 1.f + t);
    delta = (u > 20.f) ? u : -__logf(p);
}

// ---------------- scratch ----------------
__device__ float g_z  [BB*LL*DI];
__device__ float g_xc [BB*LL*DI];
__device__ float g_xs [BB*K4*LL*DI];
__device__ float g_u  [BB*K4*LL*DI];
__device__ float g_Bv [BB*K4*LL*NN];
__device__ float g_Cv [BB*K4*LL*NN];
__device__ float g_y  [BB*K4*LL*DI];
__device__ float g_cumP[BB*K4*LL*DI];
__device__ float g_hend[BB*K4*NC*DI*NN];
__device__ float g_Ptot[BB*K4*NC*DI];
__device__ float g_h0  [BB*K4*NC*DI*NN];
__device__ float g_yln [BB*LL*DI];

// ---------------- K1: reverse3d + in_proj GEMM + depthwise conv + SiLU (fused) ----------------
__global__ void k_inproj(const float* __restrict__ x, const float* __restrict__ W,
                         const float* __restrict__ cw, const float* __restrict__ cb) {
    __shared__ float xr[34*64];   // rows row0-1 .. row0+32
    int co = threadIdx.x;
    float4 w[16];
    #pragma unroll
    for (int j = 0; j < 16; j++) w[j] = reinterpret_cast<const float4*>(W)[co*16 + j];
    int row0 = blockIdx.x * 32;
    for (int i = threadIdx.x; i < 34*64; i += 256) {
        int r = i >> 6, c = i & 63;
        int bl = row0 + r - 1;
        float v = 0.f;
        bool valid = true;
        if (r == 0  && (row0 & (LL-1)) == 0)        valid = false;  // l = -1
        if (r == 33 && ((row0 + 32) & (LL-1)) == 0) valid = false;  // l = LL
        if (valid) {
            int b = bl >> 12, l = bl & (LL-1);
            int cs = ((l + b) & 1) ? (63 - c) : c;
            v = x[bl*64 + cs];
        }
        xr[r*64 + c] = v;
    }
    __syncthreads();
    float w0 = 0.f, w1 = 0.f, w2 = 0.f, bias = 0.f;
    if (co < DI) { w0 = cw[co*3]; w1 = cw[co*3+1]; w2 = cw[co*3+2]; bias = cb[co]; }
    float a0 = 0.f, a1 = 0.f;
    for (int j = 0; j < 34; j++) {
        const float4* xv = reinterpret_cast<const float4*>(xr + j*64);
        float acc = 0.f;
        #pragma unroll
        for (int t = 0; t < 16; t++) {
            float4 a = w[t], q = xv[t];
            acc = fmaf(a.x,q.x,acc); acc = fmaf(a.y,q.y,acc);
            acc = fmaf(a.z,q.z,acc); acc = fmaf(a.w,q.w,acc);
        }
        if (co < DI) {
            if (j >= 2) {
                float v = bias;
                v = fmaf(w0, a0, v); v = fmaf(w1, a1, v); v = fmaf(w2, acc, v);
                float sg = __fdividef(1.f, 1.f + __expf(-v));
                g_xc[(row0 + j - 2)*DI + co] = v * sg;
            }
            a0 = a1; a1 = acc;
        } else {
            if (j >= 1 && j <= 32) g_z[(row0 + j - 1)*DI + (co - DI)] = acc;
        }
    }
}

// ---------------- K3: zigzag gather + x_proj + dt_proj ----------------
__global__ void k_proj(const int* __restrict__ zig, const float* __restrict__ xpw,
                       const float* __restrict__ dtw, const float* __restrict__ dtb) {
    __shared__ float s_xpw[36*DI];
    __shared__ float s_dtw[DI*RR];
    __shared__ float s_db[DI];
    int bk = blockIdx.y; int b = bk >> 2; int k = bk & 3;
    for (int i = threadIdx.x; i < 36*DI; i += 256) s_xpw[i] = xpw[k*36*DI + i];
    for (int i = threadIdx.x; i < DI*RR; i += 256) s_dtw[i] = dtw[k*DI*RR + i];
    for (int i = threadIdx.x; i < DI;    i += 256) s_db[i]  = dtb[k*DI + i];
    __syncthreads();
    int warp = threadIdx.x >> 5, lane = threadIdx.x & 31;
    int l = blockIdx.x * 8 + warp;
    int src = zig[k*LL + l];
    const float* xrow = g_xc + (b*LL + src)*DI;
    float x0 = xrow[lane], x1 = xrow[lane+32], x2 = xrow[lane+64], x3 = xrow[lane+96];
    int obase = (bk*LL + l)*DI;
    g_xs[obase+lane] = x0; g_xs[obase+lane+32] = x1;
    g_xs[obase+lane+64] = x2; g_xs[obase+lane+96] = x3;
    float dtr0=0.f, dtr1=0.f, dtr2=0.f, dtr3=0.f, Bval=0.f, Cval=0.f;
    #pragma unroll
    for (int c = 0; c < 36; c++) {
        const float* wp = s_xpw + c*DI + lane;
        float part = wp[0]*x0 + wp[32]*x1 + wp[64]*x2 + wp[96]*x3;
        part += __shfl_xor_sync(0xffffffffu, part, 16);
        part += __shfl_xor_sync(0xffffffffu, part, 8);
        part += __shfl_xor_sync(0xffffffffu, part, 4);
        part += __shfl_xor_sync(0xffffffffu, part, 2);
        part += __shfl_xor_sync(0xffffffffu, part, 1);
        if      (c == 0) dtr0 = part;
        else if (c == 1) dtr1 = part;
        else if (c == 2) dtr2 = part;
        else if (c == 3) dtr3 = part;
        else if (c < 20) { if (lane == c-4)  Bval = part; }
        else             { if (lane == c-20) Cval = part; }
    }
    if (lane < NN) {
        g_Bv[(bk*LL + l)*NN + lane] = Bval;
        g_Cv[(bk*LL + l)*NN + lane] = Cval;
    }
    #pragma unroll
    for (int j = 0; j < 4; j++) {
        int d = lane + 32*j;
        float u = s_db[d];
        u = fmaf(dtr0, s_dtw[d*RR+0], u);
        u = fmaf(dtr1, s_dtw[d*RR+1], u);
        u = fmaf(dtr2, s_dtw[d*RR+2], u);
        u = fmaf(dtr3, s_dtw[d*RR+3], u);
        g_u[obase + d] = u;
    }
}

// ---------------- K4: scan phase 1 (chunk-local), f32x2 fast path ----------------
__global__ void __launch_bounds__(DI) k_scan1(const float* __restrict__ A_logs,
                                              const float* __restrict__ Ds) {
    __shared__ __align__(16) float sB[CH*NN];
    __shared__ __align__(16) float sC[CH*NN];
    int c = blockIdx.x, bk = blockIdx.y;
    int k = bk & 3, d = threadIdx.x;
    int l0 = c*CH;
    for (int i = d; i < CH*NN; i += DI) {
        sB[i] = g_Bv[(bk*LL + l0)*NN + i];
        sC[i] = g_Cv[(bk*LL + l0)*NN + i];
    }
    float An[NN]; bool fast = true;
    #pragma unroll
    for (int n = 0; n < NN; n++) {
        An[n] = -__expf(A_logs[(k*DI + d)*NN + n]);
        if (fabsf(An[n] + (float)(n+1)) > 1e-3f) fast = false;
    }
    float Dval = Ds[k*DI + d];
    __syncthreads();
    float cum = 1.f;
    int base = (bk*LL + l0)*DI + d;
    int cidx = (bk*NC + c)*DI + d;
    if (fast) {
        u64 h2[NN/2];
        #pragma unroll
        for (int j = 0; j < NN/2; j++) h2[j] = 0ull;
        #pragma unroll 4
        for (int s = 0; s < CH; s++) {
            int idx = base + s*DI;
            float u = g_u[idx], xv = g_xs[idx];
            float delta, p;
            softplus_pair(u, delta, p);
            float du = delta * xv;
            cum *= p;
            g_cumP[idx] = cum;
            float psq = p*p;
            u64 p2d = pk2(psq, psq);
            u64 pn  = pk2(p, psq);
            u64 du2 = pk2(du, du);
            u64 y2  = 0ull;
            const u64* B2 = reinterpret_cast<const u64*>(sB + s*NN);
            const u64* C2 = reinterpret_cast<const u64*>(sC + s*NN);
            #pragma unroll
            for (int j = 0; j < NN/2; j++) {
                if (j) pn = mul2(pn, p2d);
                h2[j] = fma2(h2[j], pn, mul2(du2, B2[j]));
                y2 = fma2(h2[j], C2[j], y2);
            }
            float ylo, yhi; upk2(ylo, yhi, y2);
            g_y[idx] = fmaf(Dval, xv, ylo + yhi);
        }
        u64* hd = reinterpret_cast<u64*>(g_hend + cidx*NN);
        #pragma unroll
        for (int j = 0; j < NN/2; j++) hd[j] = h2[j];
    } else {
        float h[NN];
        #pragma unroll
        for (int n = 0; n < NN; n++) h[n] = 0.f;
        for (int s = 0; s < CH; s++) {
            int idx = base + s*DI;
            float u = g_u[idx], xv = g_xs[idx];
            float delta, p;
            softplus_pair(u, delta, p);
            float du = delta * xv;
            cum *= p;
            g_cumP[idx] = cum;
            float y = 0.f;
            #pragma unroll
            for (int n = 0; n < NN; n++) {
                float dA = __expf(delta * An[n]);
                h[n] = fmaf(h[n], dA, du * sB[s*NN + n]);
                y = fmaf(h[n], sC[s*NN + n], y);
            }
            g_y[idx] = fmaf(Dval, xv, y);
        }
        #pragma unroll
        for (int n = 0; n < NN; n++) g_hend[cidx*NN + n] = h[n];
    }
    g_Ptot[cidx] = cum;
}

// ---------------- K5: chunk combine — warp-shuffle two-level scan ----------------
// one warp per (bk,d) lane; 4 chunks per thread; block 256 = 8 warps
__global__ void __launch_bounds__(256) k_comb(const float* __restrict__ A_logs) {
    int gw = (blockIdx.x * 256 + threadIdx.x) >> 5;  // 0 .. BB*K4*DI-1
    int lane = threadIdx.x & 31;
    int bk = gw >> 7;
    int d  = gw & (DI-1);
    int k  = bk & 3;

    float An[NN]; bool fast = true;
    #pragma unroll
    for (int n = 0; n < NN; n++) {
        An[n] = -__expf(__ldg(&A_logs[(k*DI + d)*NN + n]));
        if (fabsf(An[n] + (float)(n+1)) > 1e-3f) fast = false;
    }
    int base = bk*NC*DI + d;
    int c0 = lane * CPL;

    // Phase A: serial segment aggregate over this lane's CPL chunks
    float F[NN], H[NN];
    #pragma unroll
    for (int n = 0; n < NN; n++) { F[n] = 1.f; H[n] = 0.f; }
    #pragma unroll
    for (int j = 0; j < CPL; j++) {
        int cidx = base + (c0 + j)*DI;
        float P = __ldg(&g_Ptot[cidx]);
        const float4* he4 = reinterpret_cast<const float4*>(g_hend + (size_t)cidx*NN);
        float4 e0 = __ldg(he4+0), e1 = __ldg(he4+1), e2 = __ldg(he4+2), e3 = __ldg(he4+3);
        float he[NN] = {e0.x,e0.y,e0.z,e0.w, e1.x,e1.y,e1.z,e1.w,
                        e2.x,e2.y,e2.z,e2.w, e3.x,e3.y,e3.z,e3.w};
        float f[NN];
        if (fast) {
            float pw = P; f[0] = P;
            #pragma unroll
            for (int n = 1; n < NN; n++) { pw *= P; f[n] = pw; }
        } else {
            #pragma unroll
            for (int n = 0; n < NN; n++)
                f[n] = (P > 0.f) ? __powf(P, -An[n]) : 0.f;
        }
        #pragma unroll
        for (int n = 0; n < NN; n++) {
            H[n] = fmaf(f[n], H[n], he[n]);
            F[n] *= f[n];
        }
    }

    // Phase B: warp-level inclusive scan of (F,H)
    #pragma unroll
    for (int st = 1; st < 32; st <<= 1) {
        float flo[NN], hlo[NN];
        #pragma unroll
        for (int n = 0; n < NN; n++) {
            flo[n] = __shfl_up_sync(0xffffffffu, F[n], st);
            hlo[n] = __shfl_up_sync(0xffffffffu, H[n], st);
        }
        if (lane >= st) {
            #pragma unroll
            for (int n = 0; n < NN; n++) {
                H[n] = fmaf(F[n], hlo[n], H[n]);
                F[n] *= flo[n];
            }
        }
    }

    // Phase C: exclusive prefix at segment start, then replay chunks
    float pre[NN];
    #pragma unroll
    for (int n = 0; n < NN; n++) {
        float v = __shfl_up_sync(0xffffffffu, H[n], 1);
        pre[n] = lane ? v : 0.f;
    }
    #pragma unroll
    for (int j = 0; j < CPL; j++) {
        int cidx = base + (c0 + j)*DI;
        float4* h04 = reinterpret_cast<float4*>(g_h0 + (size_t)cidx*NN);
        h04[0] = make_float4(pre[0],  pre[1],  pre[2],  pre[3]);
        h04[1] = make_float4(pre[4],  pre[5],  pre[6],  pre[7]);
        h04[2] = make_float4(pre[8],  pre[9],  pre[10], pre[11]);
        h04[3] = make_float4(pre[12], pre[13], pre[14], pre[15]);
        if (j < CPL-1) {
            float P = __ldg(&g_Ptot[cidx]);
            const float4* he4 = reinterpret_cast<const float4*>(g_hend + (size_t)cidx*NN);
            float4 e0 = __ldg(he4+0), e1 = __ldg(he4+1), e2 = __ldg(he4+2), e3 = __ldg(he4+3);
            float he[NN] = {e0.x,e0.y,e0.z,e0.w, e1.x,e1.y,e1.z,e1.w,
                            e2.x,e2.y,e2.z,e2.w, e3.x,e3.y,e3.z,e3.w};
            float f[NN];
            if (fast) {
                float pw = P; f[0] = P;
                #pragma unroll
                for (int n = 1; n < NN; n++) { pw *= P; f[n] = pw; }
            } else {
                #pragma unroll
                for (int n = 0; n < NN; n++)
                    f[n] = (P > 0.f) ? __powf(P, -An[n]) : 0.f;
            }
            #pragma unroll
            for (int n = 0; n < NN; n++)
                pre[n] = fmaf(f[n], pre[n], he[n]);
        }
    }
}

// ---------------- K6: correction, f32x2 fast path ----------------
__global__ void __launch_bounds__(DI) k_corr(const float* __restrict__ A_logs) {
    __shared__ __align__(16) float sC[CH*NN];
    int c = blockIdx.x + 1, bk = blockIdx.y;
    int k = bk & 3, d = threadIdx.x;
    int l0 = c*CH;
    for (int i = d; i < CH*NN; i += DI) sC[i] = g_Cv[(bk*LL + l0)*NN + i];
    float An[NN]; bool fast = true;
    #pragma unroll
    for (int n = 0; n < NN; n++) {
        An[n] = -__expf(A_logs[(k*DI + d)*NN + n]);
        if (fabsf(An[n] + (float)(n+1)) > 1e-3f) fast = false;
    }
    int cidx = (bk*NC + c)*DI + d;
    float h0[NN];
    #pragma unroll
    for (int n = 0; n < NN; n++) h0[n] = g_h0[cidx*NN + n];
    __syncthreads();
    int base = (bk*LL + l0)*DI + d;
    if (fast) {
        u64 h02[NN/2];
        #pragma unroll
        for (int j = 0; j < NN/2; j++) h02[j] = pk2(h0[2*j], h0[2*j+1]);
        #pragma unroll 4
        for (int s = 0; s < CH; s++) {
            int idx = base + s*DI;
            float cp = g_cumP[idx];
            float cpsq = cp*cp;
            u64 sq2 = pk2(cpsq, cpsq);
            u64 pn  = pk2(cp, cpsq);
            u64 acc2 = 0ull;
            const u64* C2 = reinterpret_cast<const u64*>(sC + s*NN);
            #pragma unroll
            for (int j = 0; j < NN/2; j++) {
                if (j) pn = mul2(pn, sq2);
                acc2 = fma2(pn, mul2(h02[j], C2[j]), acc2);
            }
            float lo, hi; upk2(lo, hi, acc2);
            g_y[idx] += lo + hi;
        }
    } else {
        for (int s = 0; s < CH; s++) {
            int idx = base + s*DI;
            float cp = g_cumP[idx];
            float acc = 0.f;
            if (cp > 0.f) {
                #pragma unroll
                for (int n = 0; n < NN; n++)
                    acc = fmaf(__powf(cp, -An[n]), h0[n]*sC[s*NN+n], acc);
            }
            g_y[idx] += acc;
        }
    }
}

// ---------------- K7: inverse zigzag sum + LayerNorm + silu(z) gate ----------------
__global__ void k_gln(const int* __restrict__ zb, const float* __restrict__ lnw,
                      const float* __restrict__ lnb) {
    int bl = blockIdx.x;
    int b = bl >> 12, l = bl & (LL-1);
    int d = threadIdx.x;
    float acc = 0.f;
    #pragma unroll
    for (int i = 0; i < 8; i++) {
        int kk = i & 3;
        int src = zb[i*LL + l];
        acc += g_y[((b*K4 + kk)*LL + src)*DI + d];
    }
    float s1 = acc, s2 = acc*acc;
    #pragma unroll
    for (int o = 16; o > 0; o >>= 1) {
        s1 += __shfl_xor_sync(0xffffffffu, s1, o);
        s2 += __shfl_xor_sync(0xffffffffu, s2, o);
    }
    __shared__ float r1[4], r2[4];
    int warp = d >> 5, lane = d & 31;
    if (lane == 0) { r1[warp] = s1; r2[warp] = s2; }
    __syncthreads();
    float S1 = r1[0]+r1[1]+r1[2]+r1[3];
    float S2 = r2[0]+r2[1]+r2[2]+r2[3];
    float mu = S1 * (1.f/DI);
    float var = S2 * (1.f/DI) - mu*mu;
    float yn = (acc - mu) * rsqrtf(var + 1e-5f) * lnw[d] + lnb[d];
    float zv = g_z[bl*DI + d];
    float sg = __fdividef(1.f, 1.f + __expf(-zv));
    g_yln[bl*DI + d] = yn * (zv * sg);
}

// ---------------- K8: out_proj GEMM + reverse3d, 32-row amortized ----------------
__global__ void k_out(const float* __restrict__ Wout, float* __restrict__ out) {
    __shared__ float s_y[32*DI];
    __shared__ float s_part[32*DI];
    int t = threadIdx.x;                 // 128
    int bl0 = blockIdx.x * 32;
    const float4* src = reinterpret_cast<const float4*>(g_yln + bl0*DI);
    float4* dst = reinterpret_cast<float4*>(s_y);
    #pragma unroll
    for (int i = 0; i < 8; i++) dst[t + 128*i] = src[t + 128*i];
    int co = t & 63, half = t >> 6;
    float4 w[16];
    const float4* wp = reinterpret_cast<const float4*>(Wout + co*DI + half*64);
    #pragma unroll
    for (int j = 0; j < 16; j++) w[j] = wp[j];
    __syncthreads();
    for (int r = 0; r < 32; r++) {
        const float4* yv = reinterpret_cast<const float4*>(s_y + r*DI + half*64);
        float acc = 0.f;
        #pragma unroll
        for (int j = 0; j < 16; j++) {
            float4 a = w[j], q = yv[j];
            acc = fmaf(a.x,q.x,acc); acc = fmaf(a.y,q.y,acc);
            acc = fmaf(a.z,q.z,acc); acc = fmaf(a.w,q.w,acc);
        }
        s_part[r*DI + t] = acc;
    }
    __syncthreads();
    for (int i = t; i < 32*64; i += 128) {
        int r = i >> 6, c = i & 63;
        float v = s_part[r*DI + c] + s_part[r*DI + 64 + c];
        int bl = bl0 + r;
        int b = bl >> 12, l = bl & (LL-1);
        int cdst = ((l + b) & 1) ? (63 - c) : c;
        out[bl*DM + cdst] = v;
    }
}

// ---------------- launch ----------------
extern "C" void kernel_launch(void* const* d_in, const int* in_sizes, int n_in,
                              void* d_out, int out_size) {
    const float* x        = (const float*)d_in[0];
    const int*   zig_path = (const int*)  d_in[1];
    const int*   zig_back = (const int*)  d_in[2];
    const float* in_proj  = (const float*)d_in[3];
    const float* conv_w   = (const float*)d_in[4];
    const float* conv_b   = (const float*)d_in[5];
    const float* xpw      = (const float*)d_in[6];
    const float* dtw      = (const float*)d_in[7];
    const float* dtb      = (const float*)d_in[8];
    const float* A_logs   = (const float*)d_in[9];
    const float* Ds       = (const float*)d_in[10];
    const float* lnw      = (const float*)d_in[11];
    const float* lnb      = (const float*)d_in[12];
    const float* outw     = (const float*)d_in[13];
    float* out = (float*)d_out;

    k_inproj<<<(BB*LL)/32, 256>>>(x, in_proj, conv_w, conv_b);
    k_proj  <<<dim3(LL/8, BB*K4), 256>>>(zig_path, xpw, dtw, dtb);
    k_scan1 <<<dim3(NC, BB*K4), DI>>>(A_logs, Ds);
    k_comb  <<<(BB*K4*DI*32)/256, 256>>>(A_logs);
    k_corr  <<<dim3(NC-1, BB*K4), DI>>>(A_logs);
    k_gln   <<<BB*LL, DI>>>(zig_back, lnw, lnb);
    k_out   <<<(BB*LL)/32, 128>>>(outw, out);
}

// round 14
// speedup vs baseline: 1.0016x; 1.0002x over previous
#include <cuda_runtime.h>
#include <math.h>

#define BB 2
#define LL 4096
#define DM 64
#define DI 128
#define NN 16
#define RR 4
#define K4 4
#define NC 128  // number of chunks
#define CH 32   // chunk length (NC*CH == LL)
#define CPL (NC/32)  // chunks per lane in k_comb

typedef unsigned long long u64;

__device__ __forceinline__ u64 pk2(float lo, float hi) {
    u64 r; asm("mov.b64 %0,{%1,%2};" : "=l"(r) : "f"(lo), "f"(hi)); return r;
}
__device__ __forceinline__ void upk2(float& lo, float& hi, u64 v) {
    asm("mov.b64 {%0,%1},%2;" : "=f"(lo), "=f"(hi) : "l"(v));
}
__device__ __forceinline__ u64 fma2(u64 a, u64 b, u64 c) {
    u64 d; asm("fma.rn.f32x2 %0,%1,%2,%3;" : "=l"(d) : "l"(a), "l"(b), "l"(c)); return d;
}
__device__ __forceinline__ u64 mul2(u64 a, u64 b) {
    u64 d; asm("mul.rn.f32x2 %0,%1,%2;" : "=l"(d) : "l"(a), "l"(b)); return d;
}

// softplus + exp(-softplus) via sigmoid identity:
// p = exp(-softplus(u)) = 1/(1+e^u), delta = -log(p)
__device__ __forceinline__ void softplus_pair(float u, float& delta, float& p) {
    float t = __expf(fminf(u, 20.f));
    p = __fdividef(1.f, 1.f + t);
    delta = (u > 20.f) ? u : -__logf(p);
}

// ---------------- scratch ----------------
__device__ float g_z  [BB*LL*DI];
__device__ float g_xc [BB*LL*DI];
__device__ float g_xs [BB*K4*LL*DI];
__device__ float g_u  [BB*K4*LL*DI];
__device__ float g_Bv [BB*K4*LL*NN];
__device__ float g_Cv [BB*K4*LL*NN];
__device__ float g_y  [BB*K4*LL*DI];
__device__ float g_cumP[BB*K4*LL*DI];
__device__ float g_hend[BB*K4*NC*DI*NN];
__device__ float g_Ptot[BB*K4*NC*DI];
__device__ float g_h0  [BB*K4*NC*DI*NN];
__device__ float g_yln [BB*LL*DI];

// ---------------- K1: reverse3d + in_proj GEMM + depthwise conv + SiLU (fused) ----------------
__global__ void k_inproj(const float* __restrict__ x, const float* __restrict__ W,
                         const float* __restrict__ cw, const float* __restrict__ cb) {
    __shared__ float xr[34*64];   // rows row0-1 .. row0+32
    int co = threadIdx.x;
    float4 w[16];
    #pragma unroll
    for (int j = 0; j < 16; j++) w[j] = reinterpret_cast<const float4*>(W)[co*16 + j];
    int row0 = blockIdx.x * 32;
    for (int i = threadIdx.x; i < 34*64; i += 256) {
        int r = i >> 6, c = i & 63;
        int bl = row0 + r - 1;
        float v = 0.f;
        bool valid = true;
        if (r == 0  && (row0 & (LL-1)) == 0)        valid = false;  // l = -1
        if (r == 33 && ((row0 + 32) & (LL-1)) == 0) valid = false;  // l = LL
        if (valid) {
            int b = bl >> 12, l = bl & (LL-1);
            int cs = ((l + b) & 1) ? (63 - c) : c;
            v = x[bl*64 + cs];
        }
        xr[r*64 + c] = v;
    }
    __syncthreads();
    float w0 = 0.f, w1 = 0.f, w2 = 0.f, bias = 0.f;
    if (co < DI) { w0 = cw[co*3]; w1 = cw[co*3+1]; w2 = cw[co*3+2]; bias = cb[co]; }
    float a0 = 0.f, a1 = 0.f;
    for (int j = 0; j < 34; j++) {
        const float4* xv = reinterpret_cast<const float4*>(xr + j*64);
        float acc = 0.f;
        #pragma unroll
        for (int t = 0; t < 16; t++) {
            float4 a = w[t], q = xv[t];
            acc = fmaf(a.x,q.x,acc); acc = fmaf(a.y,q.y,acc);
            acc = fmaf(a.z,q.z,acc); acc = fmaf(a.w,q.w,acc);
        }
        if (co < DI) {
            if (j >= 2) {
                float v = bias;
                v = fmaf(w0, a0, v); v = fmaf(w1, a1, v); v = fmaf(w2, acc, v);
                float sg = __fdividef(1.f, 1.f + __expf(-v));
                g_xc[(row0 + j - 2)*DI + co] = v * sg;
            }
            a0 = a1; a1 = acc;
        } else {
            if (j >= 1 && j <= 32) g_z[(row0 + j - 1)*DI + (co - DI)] = acc;
        }
    }
}

// ---------------- K3: zigzag gather + x_proj + dt_proj ----------------
__global__ void k_proj(const int* __restrict__ zig, const float* __restrict__ xpw,
                       const float* __restrict__ dtw, const float* __restrict__ dtb) {
    __shared__ float s_xpw[36*DI];
    __shared__ float s_dtw[DI*RR];
    __shared__ float s_db[DI];
    int bk = blockIdx.y; int b = bk >> 2; int k = bk & 3;
    for (int i = threadIdx.x; i < 36*DI; i += 256) s_xpw[i] = xpw[k*36*DI + i];
    for (int i = threadIdx.x; i < DI*RR; i += 256) s_dtw[i] = dtw[k*DI*RR + i];
    for (int i = threadIdx.x; i < DI;    i += 256) s_db[i]  = dtb[k*DI + i];
    __syncthreads();
    int warp = threadIdx.x >> 5, lane = threadIdx.x & 31;
    int l = blockIdx.x * 8 + warp;
    int src = zig[k*LL + l];
    const float* xrow = g_xc + (b*LL + src)*DI;
    float x0 = xrow[lane], x1 = xrow[lane+32], x2 = xrow[lane+64], x3 = xrow[lane+96];
    int obase = (bk*LL + l)*DI;
    g_xs[obase+lane] = x0; g_xs[obase+lane+32] = x1;
    g_xs[obase+lane+64] = x2; g_xs[obase+lane+96] = x3;
    float dtr0=0.f, dtr1=0.f, dtr2=0.f, dtr3=0.f, Bval=0.f, Cval=0.f;
    #pragma unroll
    for (int c = 0; c < 36; c++) {
        const float* wp = s_xpw + c*DI + lane;
        float part = wp[0]*x0 + wp[32]*x1 + wp[64]*x2 + wp[96]*x3;
        part += __shfl_xor_sync(0xffffffffu, part, 16);
        part += __shfl_xor_sync(0xffffffffu, part, 8);
        part += __shfl_xor_sync(0xffffffffu, part, 4);
        part += __shfl_xor_sync(0xffffffffu, part, 2);
        part += __shfl_xor_sync(0xffffffffu, part, 1);
        if      (c == 0) dtr0 = part;
        else if (c == 1) dtr1 = part;
        else if (c == 2) dtr2 = part;
        else if (c == 3) dtr3 = part;
        else if (c < 20) { if (lane == c-4)  Bval = part; }
        else             { if (lane == c-20) Cval = part; }
    }
    if (lane < NN) {
        g_Bv[(bk*LL + l)*NN + lane] = Bval;
        g_Cv[(bk*LL + l)*NN + lane] = Cval;
    }
    #pragma unroll
    for (int j = 0; j < 4; j++) {
        int d = lane + 32*j;
        float u = s_db[d];
        u = fmaf(dtr0, s_dtw[d*RR+0], u);
        u = fmaf(dtr1, s_dtw[d*RR+1], u);
        u = fmaf(dtr2, s_dtw[d*RR+2], u);
        u = fmaf(dtr3, s_dtw[d*RR+3], u);
        g_u[obase + d] = u;
    }
}

// ---------------- K4: scan phase 1 (chunk-local), f32x2 fast path ----------------
__global__ void __launch_bounds__(DI) k_scan1(const float* __restrict__ A_logs,
                                              const float* __restrict__ Ds) {
    __shared__ __align__(16) float sB[CH*NN];
    __shared__ __align__(16) float sC[CH*NN];
    int c = blockIdx.x, bk = blockIdx.y;
    int k = bk & 3, d = threadIdx.x;
    int l0 = c*CH;
    for (int i = d; i < CH*NN; i += DI) {
        sB[i] = g_Bv[(bk*LL + l0)*NN + i];
        sC[i] = g_Cv[(bk*LL + l0)*NN + i];
    }
    float An[NN]; bool fast = true;
    #pragma unroll
    for (int n = 0; n < NN; n++) {
        An[n] = -__expf(A_logs[(k*DI + d)*NN + n]);
        if (fabsf(An[n] + (float)(n+1)) > 1e-3f) fast = false;
    }
    float Dval = Ds[k*DI + d];
    __syncthreads();
    float cum = 1.f;
    int base = (bk*LL + l0)*DI + d;
    int cidx = (bk*NC + c)*DI + d;
    if (fast) {
        u64 h2[NN/2];
        #pragma unroll
        for (int j = 0; j < NN/2; j++) h2[j] = 0ull;
        #pragma unroll 4
        for (int s = 0; s < CH; s++) {
            int idx = base + s*DI;
            float u = g_u[idx], xv = g_xs[idx];
            float delta, p;
            softplus_pair(u, delta, p);
            float du = delta * xv;
            cum *= p;
            g_cumP[idx] = cum;
            float psq = p*p;
            u64 p2d = pk2(psq, psq);
            u64 pn  = pk2(p, psq);
            u64 du2 = pk2(du, du);
            u64 y2  = 0ull;
            const u64* B2 = reinterpret_cast<const u64*>(sB + s*NN);
            const u64* C2 = reinterpret_cast<const u64*>(sC + s*NN);
            #pragma unroll
            for (int j = 0; j < NN/2; j++) {
                if (j) pn = mul2(pn, p2d);
                h2[j] = fma2(h2[j], pn, mul2(du2, B2[j]));
                y2 = fma2(h2[j], C2[j], y2);
            }
            float ylo, yhi; upk2(ylo, yhi, y2);
            g_y[idx] = fmaf(Dval, xv, ylo + yhi);
        }
        u64* hd = reinterpret_cast<u64*>(g_hend + cidx*NN);
        #pragma unroll
        for (int j = 0; j < NN/2; j++) hd[j] = h2[j];
    } else {
        float h[NN];
        #pragma unroll
        for (int n = 0; n < NN; n++) h[n] = 0.f;
        for (int s = 0; s < CH; s++) {
            int idx = base + s*DI;
            float u = g_u[idx], xv = g_xs[idx];
            float delta, p;
            softplus_pair(u, delta, p);
            float du = delta * xv;
            cum *= p;
            g_cumP[idx] = cum;
            float y = 0.f;
            #pragma unroll
            for (int n = 0; n < NN; n++) {
                float dA = __expf(delta * An[n]);
                h[n] = fmaf(h[n], dA, du * sB[s*NN + n]);
                y = fmaf(h[n], sC[s*NN + n], y);
            }
            g_y[idx] = fmaf(Dval, xv, y);
        }
        #pragma unroll
        for (int n = 0; n < NN; n++) g_hend[cidx*NN + n] = h[n];
    }
    g_Ptot[cidx] = cum;
}

// ---------------- K5: chunk combine — warp-shuffle two-level scan ----------------
// one warp per (bk,d) lane; 4 chunks per thread; block 256 = 8 warps
__global__ void __launch_bounds__(256) k_comb(const float* __restrict__ A_logs) {
    int gw = (blockIdx.x * 256 + threadIdx.x) >> 5;  // 0 .. BB*K4*DI-1
    int lane = threadIdx.x & 31;
    int bk = gw >> 7;
    int d  = gw & (DI-1);
    int k  = bk & 3;

    float An[NN]; bool fast = true;
    #pragma unroll
    for (int n = 0; n < NN; n++) {
        An[n] = -__expf(__ldg(&A_logs[(k*DI + d)*NN + n]));
        if (fabsf(An[n] + (float)(n+1)) > 1e-3f) fast = false;
    }
    int base = bk*NC*DI + d;
    int c0 = lane * CPL;

    // Phase A: serial segment aggregate over this lane's CPL chunks
    float F[NN], H[NN];
    #pragma unroll
    for (int n = 0; n < NN; n++) { F[n] = 1.f; H[n] = 0.f; }
    #pragma unroll
    for (int j = 0; j < CPL; j++) {
        int cidx = base + (c0 + j)*DI;
        float P = __ldg(&g_Ptot[cidx]);
        const float4* he4 = reinterpret_cast<const float4*>(g_hend + (size_t)cidx*NN);
        float4 e0 = __ldg(he4+0), e1 = __ldg(he4+1), e2 = __ldg(he4+2), e3 = __ldg(he4+3);
        float he[NN] = {e0.x,e0.y,e0.z,e0.w, e1.x,e1.y,e1.z,e1.w,
                        e2.x,e2.y,e2.z,e2.w, e3.x,e3.y,e3.z,e3.w};
        float f[NN];
        if (fast) {
            float pw = P; f[0] = P;
            #pragma unroll
            for (int n = 1; n < NN; n++) { pw *= P; f[n] = pw; }
        } else {
            #pragma unroll
            for (int n = 0; n < NN; n++)
                f[n] = (P > 0.f) ? __powf(P, -An[n]) : 0.f;
        }
        #pragma unroll
        for (int n = 0; n < NN; n++) {
            H[n] = fmaf(f[n], H[n], he[n]);
            F[n] *= f[n];
        }
    }

    // Phase B: warp-level inclusive scan of (F,H)
    #pragma unroll
    for (int st = 1; st < 32; st <<= 1) {
        float flo[NN], hlo[NN];
        #pragma unroll
        for (int n = 0; n < NN; n++) {
            flo[n] = __shfl_up_sync(0xffffffffu, F[n], st);
            hlo[n] = __shfl_up_sync(0xffffffffu, H[n], st);
        }
        if (lane >= st) {
            #pragma unroll
            for (int n = 0; n < NN; n++) {
                H[n] = fmaf(F[n], hlo[n], H[n]);
                F[n] *= flo[n];
            }
        }
    }

    // Phase C: exclusive prefix at segment start, then replay chunks
    float pre[NN];
    #pragma unroll
    for (int n = 0; n < NN; n++) {
        float v = __shfl_up_sync(0xffffffffu, H[n], 1);
        pre[n] = lane ? v : 0.f;
    }
    #pragma unroll
    for (int j = 0; j < CPL; j++) {
        int cidx = base + (c0 + j)*DI;
        float4* h04 = reinterpret_cast<float4*>(g_h0 + (size_t)cidx*NN);
        h04[0] = make_float4(pre[0],  pre[1],  pre[2],  pre[3]);
        h04[1] = make_float4(pre[4],  pre[5],  pre[6],  pre[7]);
        h04[2] = make_float4(pre[8],  pre[9],  pre[10], pre[11]);
        h04[3] = make_float4(pre[12], pre[13], pre[14], pre[15]);
        if (j < CPL-1) {
            float P = __ldg(&g_Ptot[cidx]);
            const float4* he4 = reinterpret_cast<const float4*>(g_hend + (size_t)cidx*NN);
            float4 e0 = __ldg(he4+0), e1 = __ldg(he4+1), e2 = __ldg(he4+2), e3 = __ldg(he4+3);
            float he[NN] = {e0.x,e0.y,e0.z,e0.w, e1.x,e1.y,e1.z,e1.w,
                            e2.x,e2.y,e2.z,e2.w, e3.x,e3.y,e3.z,e3.w};
            float f[NN];
            if (fast) {
                float pw = P; f[0] = P;
                #pragma unroll
                for (int n = 1; n < NN; n++) { pw *= P; f[n] = pw; }
            } else {
                #pragma unroll
                for (int n = 0; n < NN; n++)
                    f[n] = (P > 0.f) ? __powf(P, -An[n]) : 0.f;
            }
            #pragma unroll
            for (int n = 0; n < NN; n++)
                pre[n] = fmaf(f[n], pre[n], he[n]);
        }
    }
}

// ---------------- K6: correction, f32x2 fast path ----------------
__global__ void __launch_bounds__(DI) k_corr(const float* __restrict__ A_logs) {
    __shared__ __align__(16) float sC[CH*NN];
    int c = blockIdx.x + 1, bk = blockIdx.y;
    int k = bk & 3, d = threadIdx.x;
    int l0 = c*CH;
    for (int i = d; i < CH*NN; i += DI) sC[i] = g_Cv[(bk*LL + l0)*NN + i];
    float An[NN]; bool fast = true;
    #pragma unroll
    for (int n = 0; n < NN; n++) {
        An[n] = -__expf(A_logs[(k*DI + d)*NN + n]);
        if (fabsf(An[n] + (float)(n+1)) > 1e-3f) fast = false;
    }
    int cidx = (bk*NC + c)*DI + d;
    float h0[NN];
    #pragma unroll
    for (int n = 0; n < NN; n++) h0[n] = g_h0[cidx*NN + n];
    __syncthreads();
    int base = (bk*LL + l0)*DI + d;
    if (fast) {
        u64 h02[NN/2];
        #pragma unroll
        for (int j = 0; j < NN/2; j++) h02[j] = pk2(h0[2*j], h0[2*j+1]);
        #pragma unroll 4
        for (int s = 0; s < CH; s++) {
            int idx = base + s*DI;
            float cp = g_cumP[idx];
            float cpsq = cp*cp;
            u64 sq2 = pk2(cpsq, cpsq);
            u64 pn  = pk2(cp, cpsq);
            u64 acc2 = 0ull;
            const u64* C2 = reinterpret_cast<const u64*>(sC + s*NN);
            #pragma unroll
            for (int j = 0; j < NN/2; j++) {
                if (j) pn = mul2(pn, sq2);
                acc2 = fma2(pn, mul2(h02[j], C2[j]), acc2);
            }
            float lo, hi; upk2(lo, hi, acc2);
            g_y[idx] += lo + hi;
        }
    } else {
        for (int s = 0; s < CH; s++) {
            int idx = base + s*DI;
            float cp = g_cumP[idx];
            float acc = 0.f;
            if (cp > 0.f) {
                #pragma unroll
                for (int n = 0; n < NN; n++)
                    acc = fmaf(__powf(cp, -An[n]), h0[n]*sC[s*NN+n], acc);
            }
            g_y[idx] += acc;
        }
    }
}

// ---------------- K7: inverse zigzag sum + LayerNorm + silu(z) gate ----------------
__global__ void k_gln(const int* __restrict__ zb, const float* __restrict__ lnw,
                      const float* __restrict__ lnb) {
    int bl = blockIdx.x;
    int b = bl >> 12, l = bl & (LL-1);
    int d = threadIdx.x;
    float acc = 0.f;
    #pragma unroll
    for (int i = 0; i < 8; i++) {
        int kk = i & 3;
        int src = zb[i*LL + l];
        acc += g_y[((b*K4 + kk)*LL + src)*DI + d];
    }
    float s1 = acc, s2 = acc*acc;
    #pragma unroll
    for (int o = 16; o > 0; o >>= 1) {
        s1 += __shfl_xor_sync(0xffffffffu, s1, o);
        s2 += __shfl_xor_sync(0xffffffffu, s2, o);
    }
    __shared__ float r1[4], r2[4];
    int warp = d >> 5, lane = d & 31;
    if (lane == 0) { r1[warp] = s1; r2[warp] = s2; }
    __syncthreads();
    float S1 = r1[0]+r1[1]+r1[2]+r1[3];
    float S2 = r2[0]+r2[1]+r2[2]+r2[3];
    float mu = S1 * (1.f/DI);
    float var = S2 * (1.f/DI) - mu*mu;
    float yn = (acc - mu) * rsqrtf(var + 1e-5f) * lnw[d] + lnb[d];
    float zv = g_z[bl*DI + d];
    float sg = __fdividef(1.f, 1.f + __expf(-zv));
    g_yln[bl*DI + d] = yn * (zv * sg);
}

// ---------------- K8: out_proj GEMM + reverse3d, 32-row amortized ----------------
__global__ void k_out(const float* __restrict__ Wout, float* __restrict__ out) {
    __shared__ float s_y[32*DI];
    __shared__ float s_part[32*DI];
    int t = threadIdx.x;                 // 128
    int bl0 = blockIdx.x * 32;
    const float4* src = reinterpret_cast<const float4*>(g_yln + bl0*DI);
    float4* dst = reinterpret_cast<float4*>(s_y);
    #pragma unroll
    for (int i = 0; i < 8; i++) dst[t + 128*i] = src[t + 128*i];
    int co = t & 63, half = t >> 6;
    float4 w[16];
    const float4* wp = reinterpret_cast<const float4*>(Wout + co*DI + half*64);
    #pragma unroll
    for (int j = 0; j < 16; j++) w[j] = wp[j];
    __syncthreads();
    for (int r = 0; r < 32; r++) {
        const float4* yv = reinterpret_cast<const float4*>(s_y + r*DI + half*64);
        float acc = 0.f;
        #pragma unroll
        for (int j = 0; j < 16; j++) {
            float4 a = w[j], q = yv[j];
            acc = fmaf(a.x,q.x,acc); acc = fmaf(a.y,q.y,acc);
            acc = fmaf(a.z,q.z,acc); acc = fmaf(a.w,q.w,acc);
        }
        s_part[r*DI + t] = acc;
    }
    __syncthreads();
    for (int i = t; i < 32*64; i += 128) {
        int r = i >> 6, c = i & 63;
        float v = s_part[r*DI + c] + s_part[r*DI + 64 + c];
        int bl = bl0 + r;
        int b = bl >> 12, l = bl & (LL-1);
        int cdst = ((l + b) & 1) ? (63 - c) : c;
        out[bl*DM + cdst] = v;
    }
}

// ---------------- launch ----------------
extern "C" void kernel_launch(void* const* d_in, const int* in_sizes, int n_in,
                              void* d_out, int out_size) {
    const float* x        = (const float*)d_in[0];
    const int*   zig_path = (const int*)  d_in[1];
    const int*   zig_back = (const int*)  d_in[2];
    const float* in_proj  = (const float*)d_in[3];
    const float* conv_w   = (const float*)d_in[4];
    const float* conv_b   = (const float*)d_in[5];
    const float* xpw      = (const float*)d_in[6];
    const float* dtw      = (const float*)d_in[7];
    const float* dtb      = (const float*)d_in[8];
    const float* A_logs   = (const float*)d_in[9];
    const float* Ds       = (const float*)d_in[10];
    const float* lnw      = (const float*)d_in[11];
    const float* lnb      = (const float*)d_in[12];
    const float* outw     = (const float*)d_in[13];
    float* out = (float*)d_out;

    k_inproj<<<(BB*LL)/32, 256>>>(x, in_proj, conv_w, conv_b);
    k_proj  <<<dim3(LL/8, BB*K4), 256>>>(zig_path, xpw, dtw, dtb);
    k_scan1 <<<dim3(NC, BB*K4), DI>>>(A_logs, Ds);
    k_comb  <<<(BB*K4*DI*32)/256, 256>>>(A_logs);
    k_corr  <<<dim3(NC-1, BB*K4), DI>>>(A_logs);
    k_gln   <<<BB*LL, DI>>>(zig_back, lnw, lnb);
    k_out   <<<(BB*LL)/32, 128>>>(outw, out);
}